// round 3
// baseline (speedup 1.0000x reference)
#include <cuda_runtime.h>
#include <cuda_bf16.h>

// RoIAlign: features [4,1024,64,64] f32, rois [2048,5] f32 -> out [2048,1024,7,7] f32
//
// Pipeline:
//  1) zero counts
//  2) compact roi indices per batch (atomic)
//  3) geometry prekernel: per (batch, slot, bin) entry write
//     {smem_ofs, out_idx (bit31 = invalid), h_ratio, w_ratio} as float4
//  4) main kernel: block = (batch, 8-channel chunk). Stage 8 planes in smem
//     with PLANE stride 4168 (== 8 mod 32) so the 4 channel lane-groups hit
//     disjoint bank shifts. Warp = 8 consecutive table entries x 4 channels
//     (x2 channel loop) -> low-conflict LDS gather AND coalesced stores.

#define B_    4
#define C_    1024
#define H_    64
#define W_    64
#define N_    2048
#define BINS  49
#define SCALE 0.0625f

#define CH        8
#define PLANE_W   65
#define PLANE     4168              // 64*65 = 4160 used, +8 pad; 4168 % 32 == 8
#define SMEM_BYTES (CH * PLANE * 4) // 133376 B
#define NTHREADS  512

__device__ int    g_roi_list[B_][N_];
__device__ int    g_roi_cnt[B_];
__device__ float4 g_geom[B_][N_ * BINS];

__global__ void zero_cnt_kernel() {
    if (threadIdx.x < B_) g_roi_cnt[threadIdx.x] = 0;
}

__global__ void build_list_kernel(const float* __restrict__ rois) {
    int n = blockIdx.x * blockDim.x + threadIdx.x;
    if (n < N_) {
        int b = (int)rois[n * 5];
        int pos = atomicAdd(&g_roi_cnt[b], 1);
        g_roi_list[b][pos] = n;
    }
}

__global__ void geom_kernel(const float* __restrict__ rois) {
    int idx = blockIdx.x * 256 + threadIdx.x;      // 0 .. N_*BINS-1
    int b = blockIdx.y;
    if (idx >= N_ * BINS) return;
    int slot = idx / BINS;
    int bin  = idx - slot * BINS;
    if (slot >= g_roi_cnt[b]) return;
    int n = g_roi_list[b][slot];

    const float* rp = rois + n * 5;
    float x1 = rp[1] * SCALE;
    float y1 = rp[2] * SCALE;
    float x2 = rp[3] * SCALE;
    float y2 = rp[4] * SCALE;
    float bw = fmaxf(x2 - x1, 0.0f) * (1.0f / 6.0f);
    float bh = fmaxf(y2 - y1, 0.0f) * (1.0f / 6.0f);
    float phf = (float)(bin / 7);
    float pwf = (float)(bin % 7);
    float h = y1 + phf * bh;
    float w = x1 + pwf * bw;

    float hstart = fminf(floorf(h), (float)(H_ - 2));
    float wstart = fminf(floorf(w), (float)(W_ - 2));
    float hr = h - hstart;
    float wr = w - wstart;
    bool valid = (h >= 0.0f) && (h < (float)H_) &&
                 (w >= 0.0f) && (w < (float)W_);
    int hs = min(max((int)hstart, 0), H_ - 2);
    int ws = min(max((int)wstart, 0), W_ - 2);

    int ofs = hs * PLANE_W + ws;
    int oi  = n * (C_ * BINS) + bin;
    if (!valid) oi |= 0x80000000;

    g_geom[b][idx] = make_float4(__int_as_float(ofs), __int_as_float(oi), hr, wr);
}

__global__ __launch_bounds__(NTHREADS, 1)
void roialign_kernel(const float* __restrict__ features,
                     float* __restrict__ out) {
    extern __shared__ float sm[];

    const int b  = blockIdx.y;
    const int c0 = blockIdx.x * CH;

    // ---- Stage CH planes into padded smem ----
    {
        const float4* src =
            (const float4*)(features + (size_t)(b * C_ + c0) * (H_ * W_));
        for (int i = threadIdx.x; i < CH * H_ * W_ / 4; i += NTHREADS) {
            float4 v = src[i];
            int c    = i >> 10;          // 1024 float4 per plane
            int rem  = i & 1023;
            int row  = rem >> 4;         // 16 float4 per row
            int col0 = (rem & 15) * 4;
            float* d = sm + c * PLANE + row * PLANE_W + col0;
            d[0] = v.x; d[1] = v.y; d[2] = v.z; d[3] = v.w;
        }
    }
    __syncthreads();

    const int E = g_roi_cnt[b] * BINS;
    const int lane = threadIdx.x & 31;
    const int warp = threadIdx.x >> 5;           // 0..15
    const int e    = lane & 7;                   // entry-sub
    const int csub = lane >> 3;                  // 0..3

    const float4* __restrict__ gt = g_geom[b];
    float* __restrict__ ob = out + (size_t)c0 * BINS + (size_t)csub * BINS;
    const float* smc = sm + csub * PLANE;

    for (int k = warp * 8; k < E; k += 16 * 8) {
        int entry = k + e;
        if (entry < E) {
            float4 g = __ldg(&gt[entry]);
            int ofs = __float_as_int(g.x);
            int oi  = __float_as_int(g.y);
            float hr = g.z, wr = g.w;
            float omh = 1.0f - hr, omw = 1.0f - wr;
            float wa = omh * omw;
            float wb = omh * wr;
            float wc = hr * omw;
            float wd = hr * wr;
            if (oi < 0) {
                wa = wb = wc = wd = 0.0f;
                oi &= 0x7FFFFFFF;
            }
            const float* p = smc + ofs;
            float* o = ob + oi;
            #pragma unroll
            for (int cc = 0; cc < 2; cc++) {
                float ul = p[0];
                float ur = p[1];
                float dl = p[PLANE_W];
                float dr = p[PLANE_W + 1];
                o[0] = wa * ul + wb * ur + wc * dl + wd * dr;
                p += 4 * PLANE;
                o += 4 * BINS;
            }
        }
    }
}

extern "C" void kernel_launch(void* const* d_in, const int* in_sizes, int n_in,
                              void* d_out, int out_size) {
    const float* features = (const float*)d_in[0];
    const float* rois     = (const float*)d_in[1];
    float* out            = (float*)d_out;

    cudaFuncSetAttribute(roialign_kernel,
                         cudaFuncAttributeMaxDynamicSharedMemorySize,
                         SMEM_BYTES);

    zero_cnt_kernel<<<1, 32>>>();
    build_list_kernel<<<N_ / 256, 256>>>(rois);
    {
        dim3 g((N_ * BINS + 255) / 256, B_);
        geom_kernel<<<g, 256>>>(rois);
    }
    {
        dim3 g(C_ / CH, B_);
        roialign_kernel<<<g, NTHREADS, SMEM_BYTES>>>(features, out);
    }
}

// round 4
// speedup vs baseline: 1.9437x; 1.9437x over previous
#include <cuda_runtime.h>
#include <cuda_bf16.h>

// RoIAlign: features [4,1024,64,64] f32, rois [2048,5] f32 -> out [2048,1024,7,7] f32
//
// Block = (batch, 8-channel chunk), 1024 threads. Features staged in smem in
// CHANNEL-INTERLEAVED layout sm[site][8] (site = h*64+w, 8 floats/site =
// 2 float4). Gather = 4x LDS.128 per thread (4 channels per corner), lane =
// (entry, channel-half): low-conflict and 4x fewer LDS instructions.
// Geometry per (roi,bin) precomputed into a float4 table by a prekernel.

#define B_    4
#define C_    1024
#define H_    64
#define W_    64
#define N_    2048
#define BINS  49
#define SCALE 0.0625f

#define CH        8
#define SMEM_BYTES (H_ * W_ * CH * 4)   // 131072 B
#define NTHREADS  1024

__device__ int    g_roi_list[B_][N_];
__device__ int    g_roi_cnt[B_];
__device__ float4 g_geom[B_][N_ * BINS];

__global__ void zero_cnt_kernel() {
    if (threadIdx.x < B_) g_roi_cnt[threadIdx.x] = 0;
}

__global__ void build_list_kernel(const float* __restrict__ rois) {
    int n = blockIdx.x * blockDim.x + threadIdx.x;
    if (n < N_) {
        int b = (int)rois[n * 5];
        int pos = atomicAdd(&g_roi_cnt[b], 1);
        g_roi_list[b][pos] = n;
    }
}

__global__ void geom_kernel(const float* __restrict__ rois) {
    int idx = blockIdx.x * 256 + threadIdx.x;      // 0 .. N_*BINS-1
    int b = blockIdx.y;
    if (idx >= N_ * BINS) return;
    int slot = idx / BINS;
    int bin  = idx - slot * BINS;
    if (slot >= g_roi_cnt[b]) return;
    int n = g_roi_list[b][slot];

    const float* rp = rois + n * 5;
    float x1 = rp[1] * SCALE;
    float y1 = rp[2] * SCALE;
    float x2 = rp[3] * SCALE;
    float y2 = rp[4] * SCALE;
    float bw = fmaxf(x2 - x1, 0.0f) * (1.0f / 6.0f);
    float bh = fmaxf(y2 - y1, 0.0f) * (1.0f / 6.0f);
    float phf = (float)(bin / 7);
    float pwf = (float)(bin % 7);
    float h = y1 + phf * bh;
    float w = x1 + pwf * bw;

    float hstart = fminf(floorf(h), (float)(H_ - 2));
    float wstart = fminf(floorf(w), (float)(W_ - 2));
    float hr = h - hstart;
    float wr = w - wstart;
    bool valid = (h >= 0.0f) && (h < (float)H_) &&
                 (w >= 0.0f) && (w < (float)W_);
    int hs = min(max((int)hstart, 0), H_ - 2);
    int ws = min(max((int)wstart, 0), W_ - 2);

    int site = hs * W_ + ws;                      // interleaved-layout site
    int oi   = n * (C_ * BINS) + bin;
    if (!valid) oi |= 0x80000000;

    g_geom[b][idx] = make_float4(__int_as_float(site), __int_as_float(oi), hr, wr);
}

__global__ __launch_bounds__(NTHREADS, 1)
void roialign_kernel(const float* __restrict__ features,
                     float* __restrict__ out) {
    extern __shared__ float4 sm4[];               // [H*W][2] float4 (8 ch/site)

    const int b  = blockIdx.y;
    const int c0 = blockIdx.x * CH;

    // ---- Stage: 8 coalesced channel streams -> interleaved sm[site][8] ----
    {
        const float* src = features + (size_t)(b * C_ + c0) * (H_ * W_);
        for (int i = threadIdx.x; i < H_ * W_; i += NTHREADS) {
            float v0 = src[i];
            float v1 = src[1 * 4096 + i];
            float v2 = src[2 * 4096 + i];
            float v3 = src[3 * 4096 + i];
            float v4 = src[4 * 4096 + i];
            float v5 = src[5 * 4096 + i];
            float v6 = src[6 * 4096 + i];
            float v7 = src[7 * 4096 + i];
            sm4[i * 2]     = make_float4(v0, v1, v2, v3);
            sm4[i * 2 + 1] = make_float4(v4, v5, v6, v7);
        }
    }
    __syncthreads();

    const int E    = g_roi_cnt[b] * BINS;
    const int lane = threadIdx.x & 31;
    const int warp = threadIdx.x >> 5;            // 0..31
    const int e    = lane >> 1;                   // 0..15 entry-sub
    const int hh   = lane & 1;                    // channel half

    const float4* __restrict__ gt = g_geom[b];
    float* __restrict__ obase = out + (size_t)(c0 + hh * 4) * BINS;

    #pragma unroll 2
    for (int base = warp * 16; base < E; base += 32 * 16) {
        int entry = base + e;
        if (entry < E) {
            float4 g = __ldg(&gt[entry]);
            int s   = __float_as_int(g.x);
            int oi  = __float_as_int(g.y);
            float hr = g.z, wr = g.w;
            float omh = 1.0f - hr, omw = 1.0f - wr;
            float wa = omh * omw;
            float wb = omh * wr;
            float wc = hr * omw;
            float wd = hr * wr;
            if (oi < 0) {
                wa = wb = wc = wd = 0.0f;
                oi &= 0x7FFFFFFF;
            }
            int p = s * 2 + hh;
            float4 ul = sm4[p];
            float4 ur = sm4[p + 2];
            float4 dl = sm4[p + 2 * W_];
            float4 dr = sm4[p + 2 * W_ + 2];

            float* o = obase + oi;
            o[0 * BINS] = wa * ul.x + wb * ur.x + wc * dl.x + wd * dr.x;
            o[1 * BINS] = wa * ul.y + wb * ur.y + wc * dl.y + wd * dr.y;
            o[2 * BINS] = wa * ul.z + wb * ur.z + wc * dl.z + wd * dr.z;
            o[3 * BINS] = wa * ul.w + wb * ur.w + wc * dl.w + wd * dr.w;
        }
    }
}

extern "C" void kernel_launch(void* const* d_in, const int* in_sizes, int n_in,
                              void* d_out, int out_size) {
    const float* features = (const float*)d_in[0];
    const float* rois     = (const float*)d_in[1];
    float* out            = (float*)d_out;

    cudaFuncSetAttribute(roialign_kernel,
                         cudaFuncAttributeMaxDynamicSharedMemorySize,
                         SMEM_BYTES);

    zero_cnt_kernel<<<1, 32>>>();
    build_list_kernel<<<N_ / 256, 256>>>(rois);
    {
        dim3 g((N_ * BINS + 255) / 256, B_);
        geom_kernel<<<g, 256>>>(rois);
    }
    {
        dim3 g(C_ / CH, B_);
        roialign_kernel<<<g, NTHREADS, SMEM_BYTES>>>(features, out);
    }
}

// round 5
// speedup vs baseline: 2.3068x; 1.1868x over previous
#include <cuda_runtime.h>
#include <cuda_bf16.h>

// RoIAlign: features [4,1024,64,64] f32, rois [2048,5] f32 -> out [2048,1024,7,7] f32
//
// Block = (batch, 4-channel chunk), 1024 threads, 64 KB smem -> 2 CTAs/SM
// (100% occupancy target). Features staged channel-interleaved sm[site] =
// float4(c0..c3). Lane = table entry: per iteration 1 LDG.128 (geom),
// 4 LDS.128 (corners, all 4 channels), 4 STG.32 (128 B contiguous runs).
// Geometry per (roi,bin) precomputed by a prekernel.

#define B_    4
#define C_    1024
#define H_    64
#define W_    64
#define N_    2048
#define BINS  49
#define SCALE 0.0625f

#define CH        4
#define SMEM_BYTES (H_ * W_ * CH * 4)   // 65536 B
#define NTHREADS  1024

__device__ int    g_roi_list[B_][N_];
__device__ int    g_roi_cnt[B_];
__device__ float4 g_geom[B_][N_ * BINS];

__global__ void zero_cnt_kernel() {
    if (threadIdx.x < B_) g_roi_cnt[threadIdx.x] = 0;
}

__global__ void build_list_kernel(const float* __restrict__ rois) {
    int n = blockIdx.x * blockDim.x + threadIdx.x;
    if (n < N_) {
        int b = (int)rois[n * 5];
        int pos = atomicAdd(&g_roi_cnt[b], 1);
        g_roi_list[b][pos] = n;
    }
}

__global__ void geom_kernel(const float* __restrict__ rois) {
    int idx = blockIdx.x * 256 + threadIdx.x;      // 0 .. N_*BINS-1
    int b = blockIdx.y;
    if (idx >= N_ * BINS) return;
    int slot = idx / BINS;
    int bin  = idx - slot * BINS;
    if (slot >= g_roi_cnt[b]) return;
    int n = g_roi_list[b][slot];

    const float* rp = rois + n * 5;
    float x1 = rp[1] * SCALE;
    float y1 = rp[2] * SCALE;
    float x2 = rp[3] * SCALE;
    float y2 = rp[4] * SCALE;
    float bw = fmaxf(x2 - x1, 0.0f) * (1.0f / 6.0f);
    float bh = fmaxf(y2 - y1, 0.0f) * (1.0f / 6.0f);
    float phf = (float)(bin / 7);
    float pwf = (float)(bin % 7);
    float h = y1 + phf * bh;
    float w = x1 + pwf * bw;

    float hstart = fminf(floorf(h), (float)(H_ - 2));
    float wstart = fminf(floorf(w), (float)(W_ - 2));
    float hr = h - hstart;
    float wr = w - wstart;
    bool valid = (h >= 0.0f) && (h < (float)H_) &&
                 (w >= 0.0f) && (w < (float)W_);
    int hs = min(max((int)hstart, 0), H_ - 2);
    int ws = min(max((int)wstart, 0), W_ - 2);

    int site = hs * W_ + ws;                      // interleaved-layout site
    int oi   = n * (C_ * BINS) + bin;
    if (!valid) oi |= 0x80000000;

    g_geom[b][idx] = make_float4(__int_as_float(site), __int_as_float(oi), hr, wr);
}

__global__ __launch_bounds__(NTHREADS, 2)
void roialign_kernel(const float* __restrict__ features,
                     float* __restrict__ out) {
    __shared__ float4 sm4[H_ * W_];               // [site] -> 4 channels

    const int b  = blockIdx.y;
    const int c0 = blockIdx.x * CH;

    // ---- Stage: 4 coalesced channel streams -> interleaved sm[site][4] ----
    {
        const float* src = features + (size_t)(b * C_ + c0) * (H_ * W_);
        #pragma unroll
        for (int k = 0; k < (H_ * W_) / NTHREADS; k++) {
            int i = k * NTHREADS + threadIdx.x;
            float v0 = src[i];
            float v1 = src[1 * 4096 + i];
            float v2 = src[2 * 4096 + i];
            float v3 = src[3 * 4096 + i];
            sm4[i] = make_float4(v0, v1, v2, v3);
        }
    }
    __syncthreads();

    const int E    = g_roi_cnt[b] * BINS;
    const int lane = threadIdx.x & 31;
    const int warp = threadIdx.x >> 5;            // 0..31

    const float4* __restrict__ gt = g_geom[b];
    float* __restrict__ obase = out + (size_t)c0 * BINS;

    for (int base = warp * 32; base < E; base += 32 * 32) {
        int entry = base + lane;
        if (entry < E) {
            float4 g = __ldg(&gt[entry]);
            int s   = __float_as_int(g.x);
            int oi  = __float_as_int(g.y);
            float hr = g.z, wr = g.w;
            float omh = 1.0f - hr, omw = 1.0f - wr;
            float wa = omh * omw;
            float wb = omh * wr;
            float wc = hr * omw;
            float wd = hr * wr;
            if (oi < 0) {
                wa = wb = wc = wd = 0.0f;
                oi &= 0x7FFFFFFF;
            }
            float4 ul = sm4[s];
            float4 ur = sm4[s + 1];
            float4 dl = sm4[s + W_];
            float4 dr = sm4[s + W_ + 1];

            float* o = obase + oi;
            o[0 * BINS] = wa * ul.x + wb * ur.x + wc * dl.x + wd * dr.x;
            o[1 * BINS] = wa * ul.y + wb * ur.y + wc * dl.y + wd * dr.y;
            o[2 * BINS] = wa * ul.z + wb * ur.z + wc * dl.z + wd * dr.z;
            o[3 * BINS] = wa * ul.w + wb * ur.w + wc * dl.w + wd * dr.w;
        }
    }
}

extern "C" void kernel_launch(void* const* d_in, const int* in_sizes, int n_in,
                              void* d_out, int out_size) {
    const float* features = (const float*)d_in[0];
    const float* rois     = (const float*)d_in[1];
    float* out            = (float*)d_out;

    zero_cnt_kernel<<<1, 32>>>();
    build_list_kernel<<<N_ / 256, 256>>>(rois);
    {
        dim3 g((N_ * BINS + 255) / 256, B_);
        geom_kernel<<<g, 256>>>(rois);
    }
    {
        dim3 g(C_ / CH, B_);
        roialign_kernel<<<g, NTHREADS>>>(features, out);
    }
}

// round 6
// speedup vs baseline: 2.4287x; 1.0529x over previous
#include <cuda_runtime.h>
#include <cuda_bf16.h>

// RoIAlign: features [4,1024,64,64] f32, rois [2048,5] f32 -> out [2048,1024,7,7] f32
//
// Block = (batch, 4-channel chunk), 1024 threads, 65 KB smem -> 2 CTAs/SM.
// Features staged channel-interleaved sm4[hs*65+ws] = float4(c0..c3); row
// stride 65 makes LDS bank-group = (hs+ws)%8 (decorrelated from column-only).
// Geometry packed to 8 B/entry: u32{invalid|hs|ws|n|bin} + u32{hrq16|wrq16}
// (16-bit fixed point ratios, abs err 3e-5). Lane = entry: per iter
// 1 LDG.64 (geom), 4 LDS.128 (4 corners x 4 channels), 4 coalesced STG.32.

#define B_    4
#define C_    1024
#define H_    64
#define W_    64
#define N_    2048
#define BINS  49
#define SCALE 0.0625f

#define CH       4
#define PLANE4   65                         // float4 row stride
#define SMEM_BYTES (H_ * PLANE4 * 16)       // 66560 B
#define NTHREADS 1024

__device__ int   g_roi_list[B_][N_];
__device__ int   g_roi_cnt[B_];
__device__ uint2 g_geom[B_][N_ * BINS];

__global__ void zero_cnt_kernel() {
    if (threadIdx.x < B_) g_roi_cnt[threadIdx.x] = 0;
}

__global__ void build_list_kernel(const float* __restrict__ rois) {
    int n = blockIdx.x * blockDim.x + threadIdx.x;
    if (n < N_) {
        int b = (int)rois[n * 5];
        int pos = atomicAdd(&g_roi_cnt[b], 1);
        g_roi_list[b][pos] = n;
    }
}

__global__ void geom_kernel(const float* __restrict__ rois) {
    int idx = blockIdx.x * 256 + threadIdx.x;      // 0 .. N_*BINS-1
    int b = blockIdx.y;
    if (idx >= N_ * BINS) return;
    int slot = idx / BINS;
    int bin  = idx - slot * BINS;
    if (slot >= g_roi_cnt[b]) return;
    int n = g_roi_list[b][slot];

    const float* rp = rois + n * 5;
    float x1 = rp[1] * SCALE;
    float y1 = rp[2] * SCALE;
    float x2 = rp[3] * SCALE;
    float y2 = rp[4] * SCALE;
    float bw = fmaxf(x2 - x1, 0.0f) * (1.0f / 6.0f);
    float bh = fmaxf(y2 - y1, 0.0f) * (1.0f / 6.0f);
    float phf = (float)(bin / 7);
    float pwf = (float)(bin % 7);
    float h = y1 + phf * bh;
    float w = x1 + pwf * bw;

    float hstart = fminf(floorf(h), (float)(H_ - 2));
    float wstart = fminf(floorf(w), (float)(W_ - 2));
    float hr = h - hstart;
    float wr = w - wstart;
    bool valid = (h >= 0.0f) && (h < (float)H_) &&
                 (w >= 0.0f) && (w < (float)W_);
    int hs = min(max((int)hstart, 0), H_ - 2);
    int ws = min(max((int)wstart, 0), W_ - 2);

    // quantize ratios to u16 fixed point (hr, wr in [0, 2))
    unsigned hrq = min((int)(hr * 32768.0f + 0.5f), 65535);
    unsigned wrq = min((int)(wr * 32768.0f + 0.5f), 65535);

    unsigned a = (unsigned)bin | ((unsigned)n << 6) |
                 ((unsigned)ws << 17) | ((unsigned)hs << 23);
    if (!valid) a |= 0x80000000u;

    g_geom[b][idx] = make_uint2(a, (hrq << 16) | wrq);
}

__global__ __launch_bounds__(NTHREADS, 2)
void roialign_kernel(const float* __restrict__ features,
                     float* __restrict__ out) {
    extern __shared__ float4 sm4[];               // [hs*65+ws] -> 4 channels

    const int b  = blockIdx.y;
    const int c0 = blockIdx.x * CH;

    // ---- Stage: 4 coalesced channel streams -> row-padded interleaved ----
    {
        const float* src = features + (size_t)(b * C_ + c0) * (H_ * W_);
        #pragma unroll
        for (int k = 0; k < (H_ * W_) / NTHREADS; k++) {
            int i = k * NTHREADS + threadIdx.x;
            int row = i >> 6;
            int col = i & 63;
            float v0 = src[i];
            float v1 = src[1 * 4096 + i];
            float v2 = src[2 * 4096 + i];
            float v3 = src[3 * 4096 + i];
            sm4[row * PLANE4 + col] = make_float4(v0, v1, v2, v3);
        }
    }
    __syncthreads();

    const int E    = g_roi_cnt[b] * BINS;
    const int lane = threadIdx.x & 31;
    const int warp = threadIdx.x >> 5;            // 0..31

    const uint2* __restrict__ gt = g_geom[b];
    float* __restrict__ obase = out + (size_t)c0 * BINS;

    for (int base = warp * 32; base < E; base += 32 * 32) {
        int entry = base + lane;
        if (entry < E) {
            uint2 g = __ldg(&gt[entry]);
            unsigned a = g.x;
            int bin = a & 63;
            int n   = (a >> 6) & 2047;
            int ws  = (a >> 17) & 63;
            int hs  = (a >> 23) & 63;
            float hr = (float)(g.y >> 16)    * (1.0f / 32768.0f);
            float wr = (float)(g.y & 0xFFFF) * (1.0f / 32768.0f);

            float omh = 1.0f - hr, omw = 1.0f - wr;
            float wa = omh * omw;
            float wb = omh * wr;
            float wc = hr * omw;
            float wd = hr * wr;
            if ((int)a < 0) { wa = wb = wc = wd = 0.0f; }

            int s = hs * PLANE4 + ws;
            float4 ul = sm4[s];
            float4 ur = sm4[s + 1];
            float4 dl = sm4[s + PLANE4];
            float4 dr = sm4[s + PLANE4 + 1];

            float* o = obase + n * (C_ * BINS) + bin;
            o[0 * BINS] = wa * ul.x + wb * ur.x + wc * dl.x + wd * dr.x;
            o[1 * BINS] = wa * ul.y + wb * ur.y + wc * dl.y + wd * dr.y;
            o[2 * BINS] = wa * ul.z + wb * ur.z + wc * dl.z + wd * dr.z;
            o[3 * BINS] = wa * ul.w + wb * ur.w + wc * dl.w + wd * dr.w;
        }
    }
}

extern "C" void kernel_launch(void* const* d_in, const int* in_sizes, int n_in,
                              void* d_out, int out_size) {
    const float* features = (const float*)d_in[0];
    const float* rois     = (const float*)d_in[1];
    float* out            = (float*)d_out;

    cudaFuncSetAttribute(roialign_kernel,
                         cudaFuncAttributeMaxDynamicSharedMemorySize,
                         SMEM_BYTES);

    zero_cnt_kernel<<<1, 32>>>();
    build_list_kernel<<<N_ / 256, 256>>>(rois);
    {
        dim3 g((N_ * BINS + 255) / 256, B_);
        geom_kernel<<<g, 256>>>(rois);
    }
    {
        dim3 g(C_ / CH, B_);
        roialign_kernel<<<g, NTHREADS, SMEM_BYTES>>>(features, out);
    }
}